// round 1
// baseline (speedup 1.0000x reference)
#include <cuda_runtime.h>
#include <math.h>

// ---------------- problem constants ----------------
static constexpr int kIN  = 128;
static constexpr int kH   = 4;
static constexpr int kC   = 64;
static constexpr int kHC  = 256;   // kH*kC
static constexpr int kOUT = 512;
static constexpr int MAXN  = 50000;
static constexpr int MAXET = 850000;   // E + N (self loops)

// ---------------- scratch (no allocs allowed) ----------------
__device__ float g_bufA[(size_t)MAXN * kHC];   // xl of current layer
__device__ float g_bufB[(size_t)MAXN * kHC];   // layer outputs (ping)
__device__ float g_bufC[(size_t)MAXN * kHC];   // layer outputs (pong)
__device__ float g_as[(size_t)MAXN * kH];
__device__ float g_ad[(size_t)MAXN * kH];
__device__ float g_p [(size_t)MAXET * kH];
__device__ float g_den[(size_t)MAXN * kH];

// ---------------- SGEMM: C[M,Nc] = A[M,K] @ B[K,Nc] (+bias, relu) ----------------
// 128x128 block tile, BK=8, 8x8 per thread, 256 threads.
__global__ __launch_bounds__(256) void sgemm_kernel(
    const float* __restrict__ A, const float* __restrict__ B, float* __restrict__ C,
    int M, int K, int Nc, const float* __restrict__ bias, int do_relu)
{
    __shared__ float As[8][128];
    __shared__ float Bs[8][128];

    const int tid = threadIdx.x;
    const int tx = tid % 16;          // 16 col groups * 8 = 128
    const int ty = tid / 16;          // 16 row groups * 8 = 128
    const int rowBase = blockIdx.y * 128;
    const int colBase = blockIdx.x * 128;

    // loader mapping
    const int aRow = tid >> 1;          // 0..127
    const int aCol = (tid & 1) * 4;     // 0 or 4
    const int bRow = tid >> 5;          // 0..7
    const int bCol = (tid & 31) * 4;    // 0..124

    float acc[8][8];
#pragma unroll
    for (int i = 0; i < 8; i++)
#pragma unroll
        for (int j = 0; j < 8; j++) acc[i][j] = 0.f;

    for (int k0 = 0; k0 < K; k0 += 8) {
        float4 av = make_float4(0.f, 0.f, 0.f, 0.f);
        int ar = rowBase + aRow;
        if (ar < M) av = *(const float4*)(A + (size_t)ar * K + k0 + aCol);
        As[aCol + 0][aRow] = av.x;
        As[aCol + 1][aRow] = av.y;
        As[aCol + 2][aRow] = av.z;
        As[aCol + 3][aRow] = av.w;

        float4 bv = make_float4(0.f, 0.f, 0.f, 0.f);
        int bc = colBase + bCol;
        if (bc < Nc) bv = *(const float4*)(B + (size_t)(k0 + bRow) * Nc + bc);
        *(float4*)&Bs[bRow][bCol] = bv;

        __syncthreads();
#pragma unroll
        for (int kk = 0; kk < 8; kk++) {
            float a[8], b[8];
#pragma unroll
            for (int i = 0; i < 8; i++) a[i] = As[kk][ty * 8 + i];
#pragma unroll
            for (int j = 0; j < 8; j++) b[j] = Bs[kk][tx * 8 + j];
#pragma unroll
            for (int i = 0; i < 8; i++)
#pragma unroll
                for (int j = 0; j < 8; j++) acc[i][j] += a[i] * b[j];
        }
        __syncthreads();
    }

#pragma unroll
    for (int i = 0; i < 8; i++) {
        int r = rowBase + ty * 8 + i;
        if (r >= M) continue;
#pragma unroll
        for (int j4 = 0; j4 < 8; j4 += 4) {
            int c = colBase + tx * 8 + j4;
            if (c >= Nc) continue;
            float4 v = make_float4(acc[i][j4], acc[i][j4 + 1], acc[i][j4 + 2], acc[i][j4 + 3]);
            if (bias) {
                v.x += bias[c];     v.y += bias[c + 1];
                v.z += bias[c + 2]; v.w += bias[c + 3];
            }
            if (do_relu) {
                v.x = fmaxf(v.x, 0.f); v.y = fmaxf(v.y, 0.f);
                v.z = fmaxf(v.z, 0.f); v.w = fmaxf(v.w, 0.f);
            }
            *(float4*)(C + (size_t)r * Nc + c) = v;
        }
    }
}

// ---------------- attention coefficients: as[n,h] = sum_c xl[n,h,c]*a_src[h,c] ----------------
// one warp per node, coalesced row read, shuffle reduce
template <int H, int CH>
__global__ void attn_coef_kernel(const float* __restrict__ xl,
                                 const float* __restrict__ a_src,
                                 const float* __restrict__ a_dst,
                                 float* __restrict__ as_n, float* __restrict__ ad_n, int N)
{
    const int HC = H * CH;
    int warp = (blockIdx.x * blockDim.x + threadIdx.x) >> 5;
    int lane = threadIdx.x & 31;
    if (warp >= N) return;

    float ss[H], sd[H];
#pragma unroll
    for (int h = 0; h < H; h++) { ss[h] = 0.f; sd[h] = 0.f; }

#pragma unroll
    for (int k = 0; k < HC / 32; k++) {
        const int h = (32 * k) / CH;   // compile-time; 32k interval never crosses a head boundary (CH=64)
        int c = lane + 32 * k;
        float v = xl[(size_t)warp * HC + c];
        ss[h] += v * a_src[c];
        sd[h] += v * a_dst[c];
    }
#pragma unroll
    for (int off = 16; off; off >>= 1) {
#pragma unroll
        for (int h = 0; h < H; h++) {
            ss[h] += __shfl_xor_sync(0xFFFFFFFFu, ss[h], off);
            sd[h] += __shfl_xor_sync(0xFFFFFFFFu, sd[h], off);
        }
    }
    if (lane == 0) {
#pragma unroll
        for (int h = 0; h < H; h++) {
            as_n[(size_t)warp * H + h] = ss[h];
            ad_n[(size_t)warp * H + h] = sd[h];
        }
    }
}

// ---------------- edge pass 1: p = exp(leaky_relu(as[src]+ad[dst])); den[dst] += p ----------------
template <int H>
__global__ void edge_num_kernel(const int* __restrict__ ei, int E, int N,
                                const float* __restrict__ as_n, const float* __restrict__ ad_n,
                                float* __restrict__ p, float* __restrict__ den)
{
    int e = blockIdx.x * blockDim.x + threadIdx.x;
    int ET = E + N;
    if (e >= ET) return;
    int s, d;
    if (e < E) { s = ei[e]; d = ei[E + e]; } else { s = d = e - E; }

    float pv[H];
#pragma unroll
    for (int h = 0; h < H; h++) {
        float l = as_n[(size_t)s * H + h] + ad_n[(size_t)d * H + h];
        l = (l > 0.f) ? l : 0.2f * l;
        pv[h] = __expf(l);
    }
    if (H == 4) {
        *(float4*)&p[(size_t)e * 4] = make_float4(pv[0], pv[1], pv[2 % H], pv[3 % H]);
        atomicAdd((float4*)&den[(size_t)d * 4], make_float4(pv[0], pv[1], pv[2 % H], pv[3 % H]));
    } else {
#pragma unroll
        for (int h = 0; h < H; h++) {
            p[(size_t)e * H + h] = pv[h];
            atomicAdd(&den[(size_t)d * H + h], pv[h]);
        }
    }
}

// ---------------- edge pass 2: out[dst] += (p/den[dst]) * xl[src], float4 vector reds ----------------
template <int H, int CH>
__global__ void edge_aggr_kernel(const int* __restrict__ ei, int E, int N,
                                 const float* __restrict__ xl,
                                 const float* __restrict__ p, const float* __restrict__ den,
                                 float* __restrict__ out)
{
    const int HC = H * CH;
    const int Q = HC / 4;           // float4 chunks per edge
    int idx = blockIdx.x * blockDim.x + threadIdx.x;
    int ET = E + N;
    int total = ET * Q;
    if (idx >= total) return;
    int e = idx / Q;
    int q = idx - e * Q;
    int s, d;
    if (e < E) { s = ei[e]; d = ei[E + e]; } else { s = d = e - E; }
    int h = (q * 4) / CH;
    float alpha = p[(size_t)e * H + h] / (den[(size_t)d * H + h] + 1e-16f);
    float4 v = *(const float4*)(xl + (size_t)s * HC + q * 4);
    v.x *= alpha; v.y *= alpha; v.z *= alpha; v.w *= alpha;
    atomicAdd((float4*)(out + (size_t)d * HC + q * 4), v);
}

// ---------------- epilogue: x = relu(x + b) ----------------
__global__ void bias_relu_kernel(float* __restrict__ x, const float* __restrict__ b,
                                 int total, int HC)
{
    int idx = blockIdx.x * blockDim.x + threadIdx.x;
    if (idx >= total) return;
    x[idx] = fmaxf(x[idx] + b[idx % HC], 0.f);
}

// ---------------- host orchestration ----------------
extern "C" void kernel_launch(void* const* d_in, const int* in_sizes, int n_in,
                              void* d_out, int out_size)
{
    const float* x   = (const float*)d_in[0];
    const int*   ei  = (const int*)d_in[1];
    const float* W1  = (const float*)d_in[2];
    const float* as1 = (const float*)d_in[3];
    const float* ad1 = (const float*)d_in[4];
    const float* b1  = (const float*)d_in[5];
    const float* W2  = (const float*)d_in[6];
    const float* as2 = (const float*)d_in[7];
    const float* ad2 = (const float*)d_in[8];
    const float* b2  = (const float*)d_in[9];
    const float* W3  = (const float*)d_in[10];
    const float* as3 = (const float*)d_in[11];
    const float* ad3 = (const float*)d_in[12];
    const float* b3  = (const float*)d_in[13];
    const float* Wfc = (const float*)d_in[14];
    const float* bfc = (const float*)d_in[15];
    float* out = (float*)d_out;

    int N  = in_sizes[0] / kIN;
    int E  = in_sizes[1] / 2;
    int ET = E + N;

    float *bufA, *bufB, *bufC, *pas, *pad, *pp, *pden;
    cudaGetSymbolAddress((void**)&bufA, g_bufA);
    cudaGetSymbolAddress((void**)&bufB, g_bufB);
    cudaGetSymbolAddress((void**)&bufC, g_bufC);
    cudaGetSymbolAddress((void**)&pas,  g_as);
    cudaGetSymbolAddress((void**)&pad,  g_ad);
    cudaGetSymbolAddress((void**)&pp,   g_p);
    cudaGetSymbolAddress((void**)&pden, g_den);

    auto gemm = [&](const float* A, const float* B, float* C, int M, int K, int Nc,
                    const float* bias, int relu) {
        dim3 grid((Nc + 127) / 128, (M + 127) / 128);
        sgemm_kernel<<<grid, 256>>>(A, B, C, M, K, Nc, bias, relu);
    };

    int attnBlocks = (N + 7) / 8;             // 8 warps/block, warp per node
    int enBlocks   = (ET + 255) / 256;

    // ---- layer 1: x[N,128] -> h1[N,256] ----
    gemm(x, W1, bufA, N, kIN, kHC, nullptr, 0);
    attn_coef_kernel<4, 64><<<attnBlocks, 256>>>(bufA, as1, ad1, pas, pad, N);
    cudaMemsetAsync(pden, 0, (size_t)N * kH * sizeof(float));
    cudaMemsetAsync(bufB, 0, (size_t)N * kHC * sizeof(float));
    edge_num_kernel<4><<<enBlocks, 256>>>(ei, E, N, pas, pad, pp, pden);
    {
        int tot = ET * (kHC / 4);
        edge_aggr_kernel<4, 64><<<(tot + 255) / 256, 256>>>(ei, E, N, bufA, pp, pden, bufB);
    }
    bias_relu_kernel<<<(N * kHC + 255) / 256, 256>>>(bufB, b1, N * kHC, kHC);

    // ---- layer 2: h1[N,256] -> h2[N,256] ----
    gemm(bufB, W2, bufA, N, kHC, kHC, nullptr, 0);
    attn_coef_kernel<4, 64><<<attnBlocks, 256>>>(bufA, as2, ad2, pas, pad, N);
    cudaMemsetAsync(pden, 0, (size_t)N * kH * sizeof(float));
    cudaMemsetAsync(bufC, 0, (size_t)N * kHC * sizeof(float));
    edge_num_kernel<4><<<enBlocks, 256>>>(ei, E, N, pas, pad, pp, pden);
    {
        int tot = ET * (kHC / 4);
        edge_aggr_kernel<4, 64><<<(tot + 255) / 256, 256>>>(ei, E, N, bufA, pp, pden, bufC);
    }
    bias_relu_kernel<<<(N * kHC + 255) / 256, 256>>>(bufC, b2, N * kHC, kHC);

    // ---- layer 3: h2[N,256] -> h3[N,64] (1 head) ----
    gemm(bufC, W3, bufA, N, kHC, kC, nullptr, 0);
    attn_coef_kernel<1, 64><<<attnBlocks, 256>>>(bufA, as3, ad3, pas, pad, N);
    cudaMemsetAsync(pden, 0, (size_t)N * sizeof(float));
    cudaMemsetAsync(bufB, 0, (size_t)N * kC * sizeof(float));
    edge_num_kernel<1><<<enBlocks, 256>>>(ei, E, N, pas, pad, pp, pden);
    {
        int tot = ET * (kC / 4);
        edge_aggr_kernel<1, 64><<<(tot + 255) / 256, 256>>>(ei, E, N, bufA, pp, pden, bufB);
    }
    bias_relu_kernel<<<(N * kC + 255) / 256, 256>>>(bufB, b3, N * kC, kC);

    // ---- final fc: h3[N,64] @ Wfc[64,512] + bfc, relu -> out ----
    gemm(bufB, Wfc, out, N, kC, kOUT, bfc, 1);
}

// round 2
// speedup vs baseline: 2.2901x; 2.2901x over previous
#include <cuda_runtime.h>
#include <math.h>

// ---------------- problem constants ----------------
static constexpr int kIN  = 128;
static constexpr int kH   = 4;
static constexpr int kC   = 64;
static constexpr int kHC  = 256;   // kH*kC
static constexpr int kOUT = 512;
static constexpr int MAXN  = 50000;
static constexpr int MAXET = 850000;   // E + N (self loops)

// ---------------- scratch (no allocs allowed) ----------------
__device__ float g_bufA[(size_t)MAXN * kHC];   // xl of current layer
__device__ float g_bufB[(size_t)MAXN * kHC];   // layer outputs (ping)
__device__ float g_bufC[(size_t)MAXN * kHC];   // layer outputs (pong)
__device__ float g_as[(size_t)MAXN * kH];
__device__ float g_ad[(size_t)MAXN * kH];
__device__ int   g_rowptr[MAXN + 1];
__device__ int   g_deg[MAXN];                  // also reused as fill cursor
__device__ int   g_adj[MAXET];                 // src ids, CSR by dst

// ---------------- SGEMM: C[M,Nc] = A[M,K] @ B[K,Nc] (+bias, relu) ----------------
__global__ __launch_bounds__(256) void sgemm_kernel(
    const float* __restrict__ A, const float* __restrict__ B, float* __restrict__ C,
    int M, int K, int Nc, const float* __restrict__ bias, int do_relu)
{
    __shared__ float As[8][128];
    __shared__ float Bs[8][128];

    const int tid = threadIdx.x;
    const int tx = tid % 16;
    const int ty = tid / 16;
    const int rowBase = blockIdx.y * 128;
    const int colBase = blockIdx.x * 128;

    const int aRow = tid >> 1;
    const int aCol = (tid & 1) * 4;
    const int bRow = tid >> 5;
    const int bCol = (tid & 31) * 4;

    float acc[8][8];
#pragma unroll
    for (int i = 0; i < 8; i++)
#pragma unroll
        for (int j = 0; j < 8; j++) acc[i][j] = 0.f;

    for (int k0 = 0; k0 < K; k0 += 8) {
        float4 av = make_float4(0.f, 0.f, 0.f, 0.f);
        int ar = rowBase + aRow;
        if (ar < M) av = *(const float4*)(A + (size_t)ar * K + k0 + aCol);
        As[aCol + 0][aRow] = av.x;
        As[aCol + 1][aRow] = av.y;
        As[aCol + 2][aRow] = av.z;
        As[aCol + 3][aRow] = av.w;

        float4 bv = make_float4(0.f, 0.f, 0.f, 0.f);
        int bc = colBase + bCol;
        if (bc < Nc) bv = *(const float4*)(B + (size_t)(k0 + bRow) * Nc + bc);
        *(float4*)&Bs[bRow][bCol] = bv;

        __syncthreads();
#pragma unroll
        for (int kk = 0; kk < 8; kk++) {
            float a[8], b[8];
#pragma unroll
            for (int i = 0; i < 8; i++) a[i] = As[kk][ty * 8 + i];
#pragma unroll
            for (int j = 0; j < 8; j++) b[j] = Bs[kk][tx * 8 + j];
#pragma unroll
            for (int i = 0; i < 8; i++)
#pragma unroll
                for (int j = 0; j < 8; j++) acc[i][j] += a[i] * b[j];
        }
        __syncthreads();
    }

#pragma unroll
    for (int i = 0; i < 8; i++) {
        int r = rowBase + ty * 8 + i;
        if (r >= M) continue;
#pragma unroll
        for (int j4 = 0; j4 < 8; j4 += 4) {
            int c = colBase + tx * 8 + j4;
            if (c >= Nc) continue;
            float4 v = make_float4(acc[i][j4], acc[i][j4 + 1], acc[i][j4 + 2], acc[i][j4 + 3]);
            if (bias) {
                v.x += bias[c];     v.y += bias[c + 1];
                v.z += bias[c + 2]; v.w += bias[c + 3];
            }
            if (do_relu) {
                v.x = fmaxf(v.x, 0.f); v.y = fmaxf(v.y, 0.f);
                v.z = fmaxf(v.z, 0.f); v.w = fmaxf(v.w, 0.f);
            }
            *(float4*)(C + (size_t)r * Nc + c) = v;
        }
    }
}

// ---------------- CSR build ----------------
__global__ void count_kernel(const int* __restrict__ ei, int E, int N, int* __restrict__ deg)
{
    int e = blockIdx.x * blockDim.x + threadIdx.x;
    int ET = E + N;
    if (e >= ET) return;
    int d = (e < E) ? ei[E + e] : (e - E);
    atomicAdd(&deg[d], 1);
}

__global__ void scan_kernel(const int* __restrict__ deg, int* __restrict__ rowptr, int N)
{
    __shared__ int sh[1024];
    __shared__ int carry;
    if (threadIdx.x == 0) carry = 0;
    __syncthreads();
    for (int base = 0; base < N; base += 1024) {
        int i = base + threadIdx.x;
        int v = (i < N) ? deg[i] : 0;
        sh[threadIdx.x] = v;
        __syncthreads();
#pragma unroll
        for (int off = 1; off < 1024; off <<= 1) {
            int t = (threadIdx.x >= off) ? sh[threadIdx.x - off] : 0;
            __syncthreads();
            sh[threadIdx.x] += t;
            __syncthreads();
        }
        if (i < N) rowptr[i + 1] = carry + sh[threadIdx.x];
        __syncthreads();
        if (threadIdx.x == 0) carry += sh[1023];
        __syncthreads();
    }
    if (threadIdx.x == 0) rowptr[0] = 0;
}

__global__ void fill_kernel(const int* __restrict__ ei, int E, int N,
                            const int* __restrict__ rowptr, int* __restrict__ cur,
                            int* __restrict__ adj)
{
    int e = blockIdx.x * blockDim.x + threadIdx.x;
    int ET = E + N;
    if (e >= ET) return;
    int s, d;
    if (e < E) { s = ei[e]; d = ei[E + e]; } else { s = d = e - E; }
    int pos = rowptr[d] + atomicAdd(&cur[d], 1);
    adj[pos] = s;
}

// ---------------- attention coefficients ----------------
template <int H, int CH>
__global__ void attn_coef_kernel(const float* __restrict__ xl,
                                 const float* __restrict__ a_src,
                                 const float* __restrict__ a_dst,
                                 float* __restrict__ as_n, float* __restrict__ ad_n, int N)
{
    const int HC = H * CH;
    int warp = (blockIdx.x * blockDim.x + threadIdx.x) >> 5;
    int lane = threadIdx.x & 31;
    if (warp >= N) return;

    float ss[H], sd[H];
#pragma unroll
    for (int h = 0; h < H; h++) { ss[h] = 0.f; sd[h] = 0.f; }

#pragma unroll
    for (int k = 0; k < HC / 32; k++) {
        const int h = (32 * k) / CH;
        int c = lane + 32 * k;
        float v = xl[(size_t)warp * HC + c];
        ss[h] += v * a_src[c];
        sd[h] += v * a_dst[c];
    }
#pragma unroll
    for (int off = 16; off; off >>= 1) {
#pragma unroll
        for (int h = 0; h < H; h++) {
            ss[h] += __shfl_xor_sync(0xFFFFFFFFu, ss[h], off);
            sd[h] += __shfl_xor_sync(0xFFFFFFFFu, sd[h], off);
        }
    }
    if (lane == 0) {
#pragma unroll
        for (int h = 0; h < H; h++) {
            as_n[(size_t)warp * H + h] = ss[h];
            ad_n[(size_t)warp * H + h] = sd[h];
        }
    }
}

// ---------------- fused gather: softmax + aggregate + bias + relu ----------------
// H=4, C=64 (HC=256): one warp per dst node, lane owns 8 floats (2 float4).
__global__ __launch_bounds__(256) void gat_gather4_kernel(
    const int* __restrict__ rowptr, const int* __restrict__ adj,
    const float* __restrict__ xl,
    const float* __restrict__ as_n, const float* __restrict__ ad_n,
    const float* __restrict__ bias, float* __restrict__ out, int N)
{
    int w = (blockIdx.x * blockDim.x + threadIdx.x) >> 5;
    int lane = threadIdx.x & 31;
    if (w >= N) return;

    const int h   = lane >> 3;          // head this lane belongs to
    const int col = lane * 8;
    const float ad = ad_n[(size_t)w * 4 + h];

    float acc[8];
#pragma unroll
    for (int i = 0; i < 8; i++) acc[i] = 0.f;
    float den = 0.f;

    int beg = rowptr[w], end = rowptr[w + 1];
    for (int j = beg; j < end; j++) {
        int s = adj[j];
        float l = as_n[(size_t)s * 4 + h] + ad;
        l = (l > 0.f) ? l : 0.2f * l;
        float a = __expf(l);
        den += a;
        const float4* row = (const float4*)(xl + (size_t)s * 256 + col);
        float4 v0 = row[0];
        float4 v1 = row[1];
        acc[0] += a * v0.x; acc[1] += a * v0.y; acc[2] += a * v0.z; acc[3] += a * v0.w;
        acc[4] += a * v1.x; acc[5] += a * v1.y; acc[6] += a * v1.z; acc[7] += a * v1.w;
    }

    float inv = 1.f / (den + 1e-16f);
    float4 o0, o1;
    o0.x = fmaxf(acc[0] * inv + bias[col + 0], 0.f);
    o0.y = fmaxf(acc[1] * inv + bias[col + 1], 0.f);
    o0.z = fmaxf(acc[2] * inv + bias[col + 2], 0.f);
    o0.w = fmaxf(acc[3] * inv + bias[col + 3], 0.f);
    o1.x = fmaxf(acc[4] * inv + bias[col + 4], 0.f);
    o1.y = fmaxf(acc[5] * inv + bias[col + 5], 0.f);
    o1.z = fmaxf(acc[6] * inv + bias[col + 6], 0.f);
    o1.w = fmaxf(acc[7] * inv + bias[col + 7], 0.f);
    float4* dst = (float4*)(out + (size_t)w * 256 + col);
    dst[0] = o0;
    dst[1] = o1;
}

// H=1, C=64: one warp per dst node, lane owns 2 floats (1 float2).
__global__ __launch_bounds__(256) void gat_gather1_kernel(
    const int* __restrict__ rowptr, const int* __restrict__ adj,
    const float* __restrict__ xl,
    const float* __restrict__ as_n, const float* __restrict__ ad_n,
    const float* __restrict__ bias, float* __restrict__ out, int N)
{
    int w = (blockIdx.x * blockDim.x + threadIdx.x) >> 5;
    int lane = threadIdx.x & 31;
    if (w >= N) return;

    const int col = lane * 2;
    const float ad = ad_n[w];

    float acc0 = 0.f, acc1 = 0.f, den = 0.f;

    int beg = rowptr[w], end = rowptr[w + 1];
    for (int j = beg; j < end; j++) {
        int s = adj[j];
        float l = as_n[s] + ad;
        l = (l > 0.f) ? l : 0.2f * l;
        float a = __expf(l);
        den += a;
        float2 v = *(const float2*)(xl + (size_t)s * 64 + col);
        acc0 += a * v.x;
        acc1 += a * v.y;
    }

    float inv = 1.f / (den + 1e-16f);
    float2 o;
    o.x = fmaxf(acc0 * inv + bias[col + 0], 0.f);
    o.y = fmaxf(acc1 * inv + bias[col + 1], 0.f);
    *(float2*)(out + (size_t)w * 64 + col) = o;
}

// ---------------- host orchestration ----------------
extern "C" void kernel_launch(void* const* d_in, const int* in_sizes, int n_in,
                              void* d_out, int out_size)
{
    const float* x   = (const float*)d_in[0];
    const int*   ei  = (const int*)d_in[1];
    const float* W1  = (const float*)d_in[2];
    const float* as1 = (const float*)d_in[3];
    const float* ad1 = (const float*)d_in[4];
    const float* b1  = (const float*)d_in[5];
    const float* W2  = (const float*)d_in[6];
    const float* as2 = (const float*)d_in[7];
    const float* ad2 = (const float*)d_in[8];
    const float* b2  = (const float*)d_in[9];
    const float* W3  = (const float*)d_in[10];
    const float* as3 = (const float*)d_in[11];
    const float* ad3 = (const float*)d_in[12];
    const float* b3  = (const float*)d_in[13];
    const float* Wfc = (const float*)d_in[14];
    const float* bfc = (const float*)d_in[15];
    float* out = (float*)d_out;

    int N  = in_sizes[0] / kIN;
    int E  = in_sizes[1] / 2;
    int ET = E + N;

    float *bufA, *bufB, *bufC, *pas, *pad;
    int *rowptr, *deg, *adj;
    cudaGetSymbolAddress((void**)&bufA, g_bufA);
    cudaGetSymbolAddress((void**)&bufB, g_bufB);
    cudaGetSymbolAddress((void**)&bufC, g_bufC);
    cudaGetSymbolAddress((void**)&pas,  g_as);
    cudaGetSymbolAddress((void**)&pad,  g_ad);
    cudaGetSymbolAddress((void**)&rowptr, g_rowptr);
    cudaGetSymbolAddress((void**)&deg,    g_deg);
    cudaGetSymbolAddress((void**)&adj,    g_adj);

    auto gemm = [&](const float* A, const float* B, float* C, int M, int K, int Nc,
                    const float* bias, int relu) {
        dim3 grid((Nc + 127) / 128, (M + 127) / 128);
        sgemm_kernel<<<grid, 256>>>(A, B, C, M, K, Nc, bias, relu);
    };

    int attnBlocks = (N + 7) / 8;
    int edgeBlocks = (ET + 255) / 256;
    int nodeWarpBlocks = (N + 7) / 8;

    // ---- CSR build (once per call) ----
    cudaMemsetAsync(deg, 0, (size_t)N * sizeof(int));
    count_kernel<<<edgeBlocks, 256>>>(ei, E, N, deg);
    scan_kernel<<<1, 1024>>>(deg, rowptr, N);
    cudaMemsetAsync(deg, 0, (size_t)N * sizeof(int));
    fill_kernel<<<edgeBlocks, 256>>>(ei, E, N, rowptr, deg, adj);

    // ---- layer 1 ----
    gemm(x, W1, bufA, N, kIN, kHC, nullptr, 0);
    attn_coef_kernel<4, 64><<<attnBlocks, 256>>>(bufA, as1, ad1, pas, pad, N);
    gat_gather4_kernel<<<nodeWarpBlocks, 256>>>(rowptr, adj, bufA, pas, pad, b1, bufB, N);

    // ---- layer 2 ----
    gemm(bufB, W2, bufA, N, kHC, kHC, nullptr, 0);
    attn_coef_kernel<4, 64><<<attnBlocks, 256>>>(bufA, as2, ad2, pas, pad, N);
    gat_gather4_kernel<<<nodeWarpBlocks, 256>>>(rowptr, adj, bufA, pas, pad, b2, bufC, N);

    // ---- layer 3 ----
    gemm(bufC, W3, bufA, N, kHC, kC, nullptr, 0);
    attn_coef_kernel<1, 64><<<attnBlocks, 256>>>(bufA, as3, ad3, pas, pad, N);
    gat_gather1_kernel<<<nodeWarpBlocks, 256>>>(rowptr, adj, bufA, pas, pad, b3, bufB, N);

    // ---- final fc ----
    gemm(bufB, Wfc, out, N, kC, kOUT, bfc, 1);
}

// round 4
// speedup vs baseline: 4.3673x; 1.9070x over previous
#include <cuda_runtime.h>
#include <math.h>
#include <stdint.h>

// ---------------- problem constants ----------------
static constexpr int kIN  = 128;
static constexpr int kH   = 4;
static constexpr int kC   = 64;
static constexpr int kHC  = 256;   // kH*kC
static constexpr int kOUT = 512;
static constexpr int MAXN  = 50000;
static constexpr int MAXET = 850000;   // E + N (self loops)

// ---------------- scratch (no allocs allowed) ----------------
__device__ float g_bufA[(size_t)MAXN * kHC];
__device__ float g_bufB[(size_t)MAXN * kHC];
__device__ float g_bufC[(size_t)MAXN * kHC];
__device__ float g_as[(size_t)MAXN * kH];
__device__ float g_ad[(size_t)MAXN * kH];
__device__ int   g_rowptr[MAXN + 1];
__device__ int   g_deg[MAXN];
__device__ int   g_adj[MAXET];
__device__ int   g_bsum[256];

// ---------------- helpers ----------------
__device__ __forceinline__ uint32_t cvt_tf32(float f) {
    uint32_t u;
    asm("cvt.rna.tf32.f32 %0, %1;" : "=r"(u) : "f"(f));
    return u;
}

__device__ __forceinline__ void mma_tf32_16x8x8(float* c, const uint32_t* a, const uint32_t* b) {
    asm volatile(
        "mma.sync.aligned.m16n8k8.row.col.f32.tf32.tf32.f32 "
        "{%0,%1,%2,%3}, {%4,%5,%6,%7}, {%8,%9}, {%0,%1,%2,%3};"
        : "+f"(c[0]), "+f"(c[1]), "+f"(c[2]), "+f"(c[3])
        : "r"(a[0]), "r"(a[1]), "r"(a[2]), "r"(a[3]), "r"(b[0]), "r"(b[1]));
}

// ---------------- tf32 mma.sync GEMM: C[M,Nc] = A[M,K] @ W[K,Nc] (+bias,relu) ----------------
// 128 x BN tile, BK=32, 256 threads = 8 warps in 2(m) x 4(n).
// Warp tile: 64(m) x BN/4(n) -> 4 m-frags x (BN/32) n-frags of m16n8k8.
template <int BN>
__global__ __launch_bounds__(256)
void tgemm_kernel(const float* __restrict__ A, const float* __restrict__ W,
                  float* __restrict__ C, int M, int K, int Nc,
                  const float* __restrict__ bias, int do_relu)
{
    static constexpr int SA = 36;       // floats per sA row (32 + 4 pad)
    static constexpr int SB = BN + 8;   // floats per sB row
    static constexpr int NT = BN / 32;  // n-frags per warp

    __shared__ uint32_t sA[128 * SA];   // [m][k]
    __shared__ uint32_t sB[32 * SB];    // [k][n]

    const int tid = threadIdx.x;
    const int wid = tid >> 5;
    const int lid = tid & 31;
    const int g   = lid >> 2;           // group id 0..7
    const int tig = lid & 3;            // thread-in-group 0..3
    const int warp_m = wid & 1;         // 0..1
    const int warp_n = wid >> 1;        // 0..3

    const int rowBase = blockIdx.y * 128;
    const int colBase = blockIdx.x * BN;

    float acc[4][NT][4];
#pragma unroll
    for (int mt = 0; mt < 4; mt++)
#pragma unroll
        for (int nt = 0; nt < NT; nt++)
#pragma unroll
            for (int i = 0; i < 4; i++) acc[mt][nt][i] = 0.f;

    for (int k0 = 0; k0 < K; k0 += 32) {
        // ---- load A tile [128 x 32] fp32 -> tf32 into sA[m][k] (row stride SA) ----
#pragma unroll
        for (int i = 0; i < 4; i++) {
            int idx = tid + 256 * i;         // 0..1023 float4s
            int m = idx >> 3, c4 = idx & 7;
            int gr = rowBase + m;
            float4 v = make_float4(0.f, 0.f, 0.f, 0.f);
            if (gr < M) v = *(const float4*)(A + (size_t)gr * K + k0 + c4 * 4);
            uint4 u = make_uint4(cvt_tf32(v.x), cvt_tf32(v.y), cvt_tf32(v.z), cvt_tf32(v.w));
            *(uint4*)(sA + m * SA + c4 * 4) = u;
        }
        // ---- load W tile [32 x BN] fp32 -> tf32 into sB[k][n] (row stride SB) ----
        static constexpr int NB = 32 * (BN / 4) / 256;   // float4 iters
#pragma unroll
        for (int i = 0; i < NB; i++) {
            int idx = tid + 256 * i;
            int k = idx / (BN / 4);
            int c4 = idx % (BN / 4);
            const float4 v = *(const float4*)(W + (size_t)(k0 + k) * Nc + colBase + c4 * 4);
            uint4 u = make_uint4(cvt_tf32(v.x), cvt_tf32(v.y), cvt_tf32(v.z), cvt_tf32(v.w));
            *(uint4*)(sB + k * SB + c4 * 4) = u;
        }
        __syncthreads();

        // ---- compute ----
#pragma unroll
        for (int kk = 0; kk < 4; kk++) {
            const int kb = kk * 8;
            uint32_t afr[4][4];
#pragma unroll
            for (int mt = 0; mt < 4; mt++) {
                int m = warp_m * 64 + mt * 16 + g;
                afr[mt][0] = sA[(m)     * SA + kb + tig];
                afr[mt][1] = sA[(m + 8) * SA + kb + tig];
                afr[mt][2] = sA[(m)     * SA + kb + tig + 4];
                afr[mt][3] = sA[(m + 8) * SA + kb + tig + 4];
            }
            uint32_t bfr[NT][2];
#pragma unroll
            for (int nt = 0; nt < NT; nt++) {
                int n = warp_n * (BN / 4) + nt * 8 + g;
                bfr[nt][0] = sB[(kb + tig)     * SB + n];
                bfr[nt][1] = sB[(kb + tig + 4) * SB + n];
            }
#pragma unroll
            for (int mt = 0; mt < 4; mt++)
#pragma unroll
                for (int nt = 0; nt < NT; nt++)
                    mma_tf32_16x8x8(acc[mt][nt], afr[mt], bfr[nt]);
        }
        __syncthreads();
    }

    // ---- epilogue: c0=C[g][2tig], c1=C[g][2tig+1], c2=C[g+8][2tig], c3=C[g+8][2tig+1] ----
#pragma unroll
    for (int mt = 0; mt < 4; mt++) {
        int row0 = rowBase + warp_m * 64 + mt * 16 + g;
        int row1 = row0 + 8;
#pragma unroll
        for (int nt = 0; nt < NT; nt++) {
            int col = colBase + warp_n * (BN / 4) + nt * 8 + tig * 2;
            float bx = 0.f, by = 0.f;
            if (bias) { bx = bias[col]; by = bias[col + 1]; }
            float2 v0 = make_float2(acc[mt][nt][0] + bx, acc[mt][nt][1] + by);
            float2 v1 = make_float2(acc[mt][nt][2] + bx, acc[mt][nt][3] + by);
            if (do_relu) {
                v0.x = fmaxf(v0.x, 0.f); v0.y = fmaxf(v0.y, 0.f);
                v1.x = fmaxf(v1.x, 0.f); v1.y = fmaxf(v1.y, 0.f);
            }
            if (row0 < M) *(float2*)(C + (size_t)row0 * Nc + col) = v0;
            if (row1 < M) *(float2*)(C + (size_t)row1 * Nc + col) = v1;
        }
    }
}

// ---------------- CSR build ----------------
__global__ void count_kernel(const int* __restrict__ ei, int E, int N, int* __restrict__ deg)
{
    int e = blockIdx.x * blockDim.x + threadIdx.x;
    int ET = E + N;
    if (e >= ET) return;
    int d = (e < E) ? ei[E + e] : (e - E);
    atomicAdd(&deg[d], 1);
}

__global__ void scan1_kernel(const int* __restrict__ deg, int* __restrict__ rowptr,
                             int* __restrict__ bsum, int N)
{
    __shared__ int sh[1024];
    int i = blockIdx.x * 1024 + threadIdx.x;
    int v = (i < N) ? deg[i] : 0;
    sh[threadIdx.x] = v;
    __syncthreads();
#pragma unroll
    for (int off = 1; off < 1024; off <<= 1) {
        int t = (threadIdx.x >= off) ? sh[threadIdx.x - off] : 0;
        __syncthreads();
        sh[threadIdx.x] += t;
        __syncthreads();
    }
    if (i < N) rowptr[i + 1] = sh[threadIdx.x];
    if (threadIdx.x == 1023) bsum[blockIdx.x] = sh[1023];
}

__global__ void scan2_kernel(int* __restrict__ bsum, int nb)
{
    if (threadIdx.x == 0) {
        int acc = 0;
        for (int i = 0; i < nb; i++) { int t = bsum[i]; bsum[i] = acc; acc += t; }
    }
}

__global__ void scan3_kernel(int* __restrict__ rowptr, const int* __restrict__ bsum, int N)
{
    int i = blockIdx.x * 1024 + threadIdx.x;
    if (i < N) rowptr[i + 1] += bsum[blockIdx.x];
    if (i == 0) rowptr[0] = 0;
}

__global__ void fill_kernel(const int* __restrict__ ei, int E, int N,
                            const int* __restrict__ rowptr, int* __restrict__ cur,
                            int* __restrict__ adj)
{
    int e = blockIdx.x * blockDim.x + threadIdx.x;
    int ET = E + N;
    if (e >= ET) return;
    int s, d;
    if (e < E) { s = ei[e]; d = ei[E + e]; } else { s = d = e - E; }
    int pos = rowptr[d] + atomicAdd(&cur[d], 1);
    adj[pos] = s;
}

// ---------------- attention coefficients ----------------
template <int H, int CH>
__global__ void attn_coef_kernel(const float* __restrict__ xl,
                                 const float* __restrict__ a_src,
                                 const float* __restrict__ a_dst,
                                 float* __restrict__ as_n, float* __restrict__ ad_n, int N)
{
    const int HC = H * CH;
    int warp = (blockIdx.x * blockDim.x + threadIdx.x) >> 5;
    int lane = threadIdx.x & 31;
    if (warp >= N) return;

    float ss[H], sd[H];
#pragma unroll
    for (int h = 0; h < H; h++) { ss[h] = 0.f; sd[h] = 0.f; }

#pragma unroll
    for (int k = 0; k < HC / 32; k++) {
        const int h = (32 * k) / CH;
        int c = lane + 32 * k;
        float v = xl[(size_t)warp * HC + c];
        ss[h] += v * a_src[c];
        sd[h] += v * a_dst[c];
    }
#pragma unroll
    for (int off = 16; off; off >>= 1) {
#pragma unroll
        for (int h = 0; h < H; h++) {
            ss[h] += __shfl_xor_sync(0xFFFFFFFFu, ss[h], off);
            sd[h] += __shfl_xor_sync(0xFFFFFFFFu, sd[h], off);
        }
    }
    if (lane == 0) {
#pragma unroll
        for (int h = 0; h < H; h++) {
            as_n[(size_t)warp * H + h] = ss[h];
            ad_n[(size_t)warp * H + h] = sd[h];
        }
    }
}

// ---------------- fused gather: softmax + aggregate + bias + relu ----------------
__global__ __launch_bounds__(256) void gat_gather4_kernel(
    const int* __restrict__ rowptr, const int* __restrict__ adj,
    const float* __restrict__ xl,
    const float* __restrict__ as_n, const float* __restrict__ ad_n,
    const float* __restrict__ bias, float* __restrict__ out, int N)
{
    int w = (blockIdx.x * blockDim.x + threadIdx.x) >> 5;
    int lane = threadIdx.x & 31;
    if (w >= N) return;

    const int h   = lane >> 3;
    const int col = lane * 8;
    const float ad = ad_n[(size_t)w * 4 + h];

    float acc[8];
#pragma unroll
    for (int i = 0; i < 8; i++) acc[i] = 0.f;
    float den = 0.f;

    int beg = rowptr[w], end = rowptr[w + 1];
    for (int j = beg; j < end; j++) {
        int s = adj[j];
        float l = as_n[(size_t)s * 4 + h] + ad;
        l = (l > 0.f) ? l : 0.2f * l;
        float a = __expf(l);
        den += a;
        const float4* row = (const float4*)(xl + (size_t)s * 256 + col);
        float4 v0 = row[0];
        float4 v1 = row[1];
        acc[0] += a * v0.x; acc[1] += a * v0.y; acc[2] += a * v0.z; acc[3] += a * v0.w;
        acc[4] += a * v1.x; acc[5] += a * v1.y; acc[6] += a * v1.z; acc[7] += a * v1.w;
    }

    float inv = 1.f / (den + 1e-16f);
    float4 o0, o1;
    o0.x = fmaxf(acc[0] * inv + bias[col + 0], 0.f);
    o0.y = fmaxf(acc[1] * inv + bias[col + 1], 0.f);
    o0.z = fmaxf(acc[2] * inv + bias[col + 2], 0.f);
    o0.w = fmaxf(acc[3] * inv + bias[col + 3], 0.f);
    o1.x = fmaxf(acc[4] * inv + bias[col + 4], 0.f);
    o1.y = fmaxf(acc[5] * inv + bias[col + 5], 0.f);
    o1.z = fmaxf(acc[6] * inv + bias[col + 6], 0.f);
    o1.w = fmaxf(acc[7] * inv + bias[col + 7], 0.f);
    float4* dst = (float4*)(out + (size_t)w * 256 + col);
    dst[0] = o0;
    dst[1] = o1;
}

__global__ __launch_bounds__(256) void gat_gather1_kernel(
    const int* __restrict__ rowptr, const int* __restrict__ adj,
    const float* __restrict__ xl,
    const float* __restrict__ as_n, const float* __restrict__ ad_n,
    const float* __restrict__ bias, float* __restrict__ out, int N)
{
    int w = (blockIdx.x * blockDim.x + threadIdx.x) >> 5;
    int lane = threadIdx.x & 31;
    if (w >= N) return;

    const int col = lane * 2;
    const float ad = ad_n[w];

    float acc0 = 0.f, acc1 = 0.f, den = 0.f;

    int beg = rowptr[w], end = rowptr[w + 1];
    for (int j = beg; j < end; j++) {
        int s = adj[j];
        float l = as_n[s] + ad;
        l = (l > 0.f) ? l : 0.2f * l;
        float a = __expf(l);
        den += a;
        float2 v = *(const float2*)(xl + (size_t)s * 64 + col);
        acc0 += a * v.x;
        acc1 += a * v.y;
    }

    float inv = 1.f / (den + 1e-16f);
    float2 o;
    o.x = fmaxf(acc0 * inv + bias[col + 0], 0.f);
    o.y = fmaxf(acc1 * inv + bias[col + 1], 0.f);
    *(float2*)(out + (size_t)w * 64 + col) = o;
}

// ---------------- host orchestration ----------------
extern "C" void kernel_launch(void* const* d_in, const int* in_sizes, int n_in,
                              void* d_out, int out_size)
{
    const float* x   = (const float*)d_in[0];
    const int*   ei  = (const int*)d_in[1];
    const float* W1  = (const float*)d_in[2];
    const float* as1 = (const float*)d_in[3];
    const float* ad1 = (const float*)d_in[4];
    const float* b1  = (const float*)d_in[5];
    const float* W2  = (const float*)d_in[6];
    const float* as2 = (const float*)d_in[7];
    const float* ad2 = (const float*)d_in[8];
    const float* b2  = (const float*)d_in[9];
    const float* W3  = (const float*)d_in[10];
    const float* as3 = (const float*)d_in[11];
    const float* ad3 = (const float*)d_in[12];
    const float* b3  = (const float*)d_in[13];
    const float* Wfc = (const float*)d_in[14];
    const float* bfc = (const float*)d_in[15];
    float* out = (float*)d_out;

    int N  = in_sizes[0] / kIN;
    int E  = in_sizes[1] / 2;
    int ET = E + N;

    float *bufA, *bufB, *bufC, *pas, *pad;
    int *rowptr, *deg, *adj, *bsum;
    cudaGetSymbolAddress((void**)&bufA, g_bufA);
    cudaGetSymbolAddress((void**)&bufB, g_bufB);
    cudaGetSymbolAddress((void**)&bufC, g_bufC);
    cudaGetSymbolAddress((void**)&pas,  g_as);
    cudaGetSymbolAddress((void**)&pad,  g_ad);
    cudaGetSymbolAddress((void**)&rowptr, g_rowptr);
    cudaGetSymbolAddress((void**)&deg,    g_deg);
    cudaGetSymbolAddress((void**)&adj,    g_adj);
    cudaGetSymbolAddress((void**)&bsum,   g_bsum);

    auto gemm = [&](const float* A, const float* W, float* C, int M, int K, int Nc,
                    const float* bias, int relu) {
        if (Nc % 128 == 0) {
            dim3 grid(Nc / 128, (M + 127) / 128);
            tgemm_kernel<128><<<grid, 256>>>(A, W, C, M, K, Nc, bias, relu);
        } else {
            dim3 grid(Nc / 64, (M + 127) / 128);
            tgemm_kernel<64><<<grid, 256>>>(A, W, C, M, K, Nc, bias, relu);
        }
    };

    int attnBlocks = (N + 7) / 8;
    int edgeBlocks = (ET + 255) / 256;
    int nodeWarpBlocks = (N + 7) / 8;
    int scanBlocks = (N + 1023) / 1024;

    // ---- CSR build ----
    cudaMemsetAsync(deg, 0, (size_t)N * sizeof(int));
    count_kernel<<<edgeBlocks, 256>>>(ei, E, N, deg);
    scan1_kernel<<<scanBlocks, 1024>>>(deg, rowptr, bsum, N);
    scan2_kernel<<<1, 32>>>(bsum, scanBlocks);
    scan3_kernel<<<scanBlocks, 1024>>>(rowptr, bsum, N);
    cudaMemsetAsync(deg, 0, (size_t)N * sizeof(int));
    fill_kernel<<<edgeBlocks, 256>>>(ei, E, N, rowptr, deg, adj);

    // ---- layer 1 ----
    gemm(x, W1, bufA, N, kIN, kHC, nullptr, 0);
    attn_coef_kernel<4, 64><<<attnBlocks, 256>>>(bufA, as1, ad1, pas, pad, N);
    gat_gather4_kernel<<<nodeWarpBlocks, 256>>>(rowptr, adj, bufA, pas, pad, b1, bufB, N);

    // ---- layer 2 ----
    gemm(bufB, W2, bufA, N, kHC, kHC, nullptr, 0);
    attn_coef_kernel<4, 64><<<attnBlocks, 256>>>(bufA, as2, ad2, pas, pad, N);
    gat_gather4_kernel<<<nodeWarpBlocks, 256>>>(rowptr, adj, bufA, pas, pad, b2, bufC, N);

    // ---- layer 3 ----
    gemm(bufC, W3, bufA, N, kHC, kC, nullptr, 0);
    attn_coef_kernel<1, 64><<<attnBlocks, 256>>>(bufA, as3, ad3, pas, pad, N);
    gat_gather1_kernel<<<nodeWarpBlocks, 256>>>(rowptr, adj, bufA, pas, pad, b3, bufB, N);

    // ---- final fc ----
    gemm(bufB, Wfc, out, N, kC, kOUT, bfc, 1);
}

// round 5
// speedup vs baseline: 5.1089x; 1.1698x over previous
#include <cuda_runtime.h>
#include <cuda_fp16.h>
#include <math.h>
#include <stdint.h>

// ---------------- problem constants ----------------
static constexpr int kIN  = 128;
static constexpr int kH   = 4;
static constexpr int kC   = 64;
static constexpr int kHC  = 256;   // kH*kC
static constexpr int kOUT = 512;
static constexpr int MAXN  = 50000;
static constexpr int MAXET = 850000;   // E + N (self loops)

// ---------------- scratch (no allocs allowed) ----------------
__device__ float g_bufA[(size_t)MAXN * kHC];   // xl (stored as half, reinterpreted)
__device__ float g_bufB[(size_t)MAXN * kHC];
__device__ float g_bufC[(size_t)MAXN * kHC];
__device__ float g_as[(size_t)MAXN * kH];
__device__ float g_ad[(size_t)MAXN * kH];
__device__ int   g_rowptr[MAXN + 1];
__device__ int   g_deg[MAXN];
__device__ int   g_adj[MAXET];
__device__ int   g_bsum[256];

// ---------------- helpers ----------------
__device__ __forceinline__ uint32_t cvt_tf32(float f) {
    uint32_t u;
    asm("cvt.rna.tf32.f32 %0, %1;" : "=r"(u) : "f"(f));
    return u;
}

__device__ __forceinline__ void mma_tf32_16x8x8(float* c, const uint32_t* a, const uint32_t* b) {
    asm volatile(
        "mma.sync.aligned.m16n8k8.row.col.f32.tf32.tf32.f32 "
        "{%0,%1,%2,%3}, {%4,%5,%6,%7}, {%8,%9}, {%0,%1,%2,%3};"
        : "+f"(c[0]), "+f"(c[1]), "+f"(c[2]), "+f"(c[3])
        : "r"(a[0]), "r"(a[1]), "r"(a[2]), "r"(a[3]), "r"(b[0]), "r"(b[1]));
}

// ---------------- tf32 mma.sync GEMM: C[M,Nc] = A[M,K] @ W[K,Nc] (+bias,relu) ----------------
// 128 x BN tile, BK=32, 256 threads = 8 warps in 2(m) x 4(n).
// HOUT: store C as __half (row stride Nc halves); else fp32.
template <int BN, bool HOUT>
__global__ __launch_bounds__(256)
void tgemm_kernel(const float* __restrict__ A, const float* __restrict__ W,
                  float* __restrict__ C, int M, int K, int Nc,
                  const float* __restrict__ bias, int do_relu)
{
    static constexpr int SA = 36;
    static constexpr int SB = BN + 8;
    static constexpr int NT = BN / 32;

    __shared__ uint32_t sA[128 * SA];   // [m][k]
    __shared__ uint32_t sB[32 * SB];    // [k][n]

    const int tid = threadIdx.x;
    const int wid = tid >> 5;
    const int lid = tid & 31;
    const int g   = lid >> 2;
    const int tig = lid & 3;
    const int warp_m = wid & 1;
    const int warp_n = wid >> 1;

    const int rowBase = blockIdx.y * 128;
    const int colBase = blockIdx.x * BN;

    float acc[4][NT][4];
#pragma unroll
    for (int mt = 0; mt < 4; mt++)
#pragma unroll
        for (int nt = 0; nt < NT; nt++)
#pragma unroll
            for (int i = 0; i < 4; i++) acc[mt][nt][i] = 0.f;

    for (int k0 = 0; k0 < K; k0 += 32) {
#pragma unroll
        for (int i = 0; i < 4; i++) {
            int idx = tid + 256 * i;
            int m = idx >> 3, c4 = idx & 7;
            int gr = rowBase + m;
            float4 v = make_float4(0.f, 0.f, 0.f, 0.f);
            if (gr < M) v = *(const float4*)(A + (size_t)gr * K + k0 + c4 * 4);
            uint4 u = make_uint4(cvt_tf32(v.x), cvt_tf32(v.y), cvt_tf32(v.z), cvt_tf32(v.w));
            *(uint4*)(sA + m * SA + c4 * 4) = u;
        }
        static constexpr int NB = 32 * (BN / 4) / 256;
#pragma unroll
        for (int i = 0; i < NB; i++) {
            int idx = tid + 256 * i;
            int k = idx / (BN / 4);
            int c4 = idx % (BN / 4);
            const float4 v = *(const float4*)(W + (size_t)(k0 + k) * Nc + colBase + c4 * 4);
            uint4 u = make_uint4(cvt_tf32(v.x), cvt_tf32(v.y), cvt_tf32(v.z), cvt_tf32(v.w));
            *(uint4*)(sB + k * SB + c4 * 4) = u;
        }
        __syncthreads();

#pragma unroll
        for (int kk = 0; kk < 4; kk++) {
            const int kb = kk * 8;
            uint32_t afr[4][4];
#pragma unroll
            for (int mt = 0; mt < 4; mt++) {
                int m = warp_m * 64 + mt * 16 + g;
                afr[mt][0] = sA[(m)     * SA + kb + tig];
                afr[mt][1] = sA[(m + 8) * SA + kb + tig];
                afr[mt][2] = sA[(m)     * SA + kb + tig + 4];
                afr[mt][3] = sA[(m + 8) * SA + kb + tig + 4];
            }
            uint32_t bfr[NT][2];
#pragma unroll
            for (int nt = 0; nt < NT; nt++) {
                int n = warp_n * (BN / 4) + nt * 8 + g;
                bfr[nt][0] = sB[(kb + tig)     * SB + n];
                bfr[nt][1] = sB[(kb + tig + 4) * SB + n];
            }
#pragma unroll
            for (int mt = 0; mt < 4; mt++)
#pragma unroll
                for (int nt = 0; nt < NT; nt++)
                    mma_tf32_16x8x8(acc[mt][nt], afr[mt], bfr[nt]);
        }
        __syncthreads();
    }

#pragma unroll
    for (int mt = 0; mt < 4; mt++) {
        int row0 = rowBase + warp_m * 64 + mt * 16 + g;
        int row1 = row0 + 8;
#pragma unroll
        for (int nt = 0; nt < NT; nt++) {
            int col = colBase + warp_n * (BN / 4) + nt * 8 + tig * 2;
            float bx = 0.f, by = 0.f;
            if (bias) { bx = bias[col]; by = bias[col + 1]; }
            float2 v0 = make_float2(acc[mt][nt][0] + bx, acc[mt][nt][1] + by);
            float2 v1 = make_float2(acc[mt][nt][2] + bx, acc[mt][nt][3] + by);
            if (do_relu) {
                v0.x = fmaxf(v0.x, 0.f); v0.y = fmaxf(v0.y, 0.f);
                v1.x = fmaxf(v1.x, 0.f); v1.y = fmaxf(v1.y, 0.f);
            }
            if (HOUT) {
                __half2* Ch = (__half2*)C;
                if (row0 < M) Ch[((size_t)row0 * Nc + col) >> 1] = __float22half2_rn(v0);
                if (row1 < M) Ch[((size_t)row1 * Nc + col) >> 1] = __float22half2_rn(v1);
            } else {
                if (row0 < M) *(float2*)(C + (size_t)row0 * Nc + col) = v0;
                if (row1 < M) *(float2*)(C + (size_t)row1 * Nc + col) = v1;
            }
        }
    }
}

// ---------------- CSR build ----------------
__global__ void count_kernel(const int* __restrict__ ei, int E, int N, int* __restrict__ deg)
{
    int e = blockIdx.x * blockDim.x + threadIdx.x;
    int ET = E + N;
    if (e >= ET) return;
    int d = (e < E) ? ei[E + e] : (e - E);
    atomicAdd(&deg[d], 1);
}

__global__ void scan1_kernel(const int* __restrict__ deg, int* __restrict__ rowptr,
                             int* __restrict__ bsum, int N)
{
    __shared__ int sh[1024];
    int i = blockIdx.x * 1024 + threadIdx.x;
    int v = (i < N) ? deg[i] : 0;
    sh[threadIdx.x] = v;
    __syncthreads();
#pragma unroll
    for (int off = 1; off < 1024; off <<= 1) {
        int t = (threadIdx.x >= off) ? sh[threadIdx.x - off] : 0;
        __syncthreads();
        sh[threadIdx.x] += t;
        __syncthreads();
    }
    if (i < N) rowptr[i + 1] = sh[threadIdx.x];
    if (threadIdx.x == 1023) bsum[blockIdx.x] = sh[1023];
}

__global__ void scan2_kernel(int* __restrict__ bsum, int nb)
{
    if (threadIdx.x == 0) {
        int acc = 0;
        for (int i = 0; i < nb; i++) { int t = bsum[i]; bsum[i] = acc; acc += t; }
    }
}

__global__ void scan3_kernel(int* __restrict__ rowptr, const int* __restrict__ bsum, int N)
{
    int i = blockIdx.x * 1024 + threadIdx.x;
    if (i < N) rowptr[i + 1] += bsum[blockIdx.x];
    if (i == 0) rowptr[0] = 0;
}

__global__ void fill_kernel(const int* __restrict__ ei, int E, int N,
                            const int* __restrict__ rowptr, int* __restrict__ cur,
                            int* __restrict__ adj)
{
    int e = blockIdx.x * blockDim.x + threadIdx.x;
    int ET = E + N;
    if (e >= ET) return;
    int s, d;
    if (e < E) { s = ei[e]; d = ei[E + e]; } else { s = d = e - E; }
    int pos = rowptr[d] + atomicAdd(&cur[d], 1);
    adj[pos] = s;
}

// ---------------- attention coefficients (half xl) ----------------
template <int H, int CH>
__global__ void attn_coef_kernel(const __half* __restrict__ xl,
                                 const float* __restrict__ a_src,
                                 const float* __restrict__ a_dst,
                                 float* __restrict__ as_n, float* __restrict__ ad_n, int N)
{
    const int HC = H * CH;
    int warp = (blockIdx.x * blockDim.x + threadIdx.x) >> 5;
    int lane = threadIdx.x & 31;
    if (warp >= N) return;

    float ss[H], sd[H];
#pragma unroll
    for (int h = 0; h < H; h++) { ss[h] = 0.f; sd[h] = 0.f; }

#pragma unroll
    for (int k = 0; k < HC / 64; k++) {
        int c2 = lane + 32 * k;                // half2 index
        const int h = (64 * k) / CH;           // CH=64: h = k
        __half2 v2 = ((const __half2*)xl)[(size_t)warp * (HC / 2) + c2];
        float2 f = __half22float2(v2);
        int col = 2 * c2;
        ss[h] += f.x * a_src[col] + f.y * a_src[col + 1];
        sd[h] += f.x * a_dst[col] + f.y * a_dst[col + 1];
    }
#pragma unroll
    for (int off = 16; off; off >>= 1) {
#pragma unroll
        for (int h = 0; h < H; h++) {
            ss[h] += __shfl_xor_sync(0xFFFFFFFFu, ss[h], off);
            sd[h] += __shfl_xor_sync(0xFFFFFFFFu, sd[h], off);
        }
    }
    if (lane == 0) {
#pragma unroll
        for (int h = 0; h < H; h++) {
            as_n[(size_t)warp * H + h] = ss[h];
            ad_n[(size_t)warp * H + h] = sd[h];
        }
    }
}

// ---------------- fused gather (half xl): softmax + aggregate + bias + relu ----------------
__device__ __forceinline__ void acc8_half(float* acc, float a, uint4 r)
{
    const __half2* hp = (const __half2*)&r;
#pragma unroll
    for (int i = 0; i < 4; i++) {
        float2 f = __half22float2(hp[i]);
        acc[2 * i]     += a * f.x;
        acc[2 * i + 1] += a * f.y;
    }
}

__global__ __launch_bounds__(256) void gat_gather4_kernel(
    const int* __restrict__ rowptr, const int* __restrict__ adj,
    const __half* __restrict__ xl,
    const float* __restrict__ as_n, const float* __restrict__ ad_n,
    const float* __restrict__ bias, float* __restrict__ out, int N)
{
    int w = (blockIdx.x * blockDim.x + threadIdx.x) >> 5;
    int lane = threadIdx.x & 31;
    if (w >= N) return;

    const int h   = lane >> 3;
    const int col = lane * 8;
    const float ad = ad_n[(size_t)w * 4 + h];

    float acc[8];
#pragma unroll
    for (int i = 0; i < 8; i++) acc[i] = 0.f;
    float den = 0.f;

    int beg = rowptr[w], end = rowptr[w + 1];
    int j = beg;
    for (; j + 1 < end; j += 2) {
        int s0 = adj[j], s1 = adj[j + 1];
        float l0 = as_n[(size_t)s0 * 4 + h] + ad;
        float l1 = as_n[(size_t)s1 * 4 + h] + ad;
        l0 = (l0 > 0.f) ? l0 : 0.2f * l0;
        l1 = (l1 > 0.f) ? l1 : 0.2f * l1;
        float a0 = __expf(l0);
        float a1 = __expf(l1);
        uint4 r0 = *(const uint4*)(xl + (size_t)s0 * 256 + col);
        uint4 r1 = *(const uint4*)(xl + (size_t)s1 * 256 + col);
        den += a0 + a1;
        acc8_half(acc, a0, r0);
        acc8_half(acc, a1, r1);
    }
    if (j < end) {
        int s = adj[j];
        float l = as_n[(size_t)s * 4 + h] + ad;
        l = (l > 0.f) ? l : 0.2f * l;
        float a = __expf(l);
        uint4 r = *(const uint4*)(xl + (size_t)s * 256 + col);
        den += a;
        acc8_half(acc, a, r);
    }

    float inv = 1.f / (den + 1e-16f);
    float4 o0, o1;
    o0.x = fmaxf(acc[0] * inv + bias[col + 0], 0.f);
    o0.y = fmaxf(acc[1] * inv + bias[col + 1], 0.f);
    o0.z = fmaxf(acc[2] * inv + bias[col + 2], 0.f);
    o0.w = fmaxf(acc[3] * inv + bias[col + 3], 0.f);
    o1.x = fmaxf(acc[4] * inv + bias[col + 4], 0.f);
    o1.y = fmaxf(acc[5] * inv + bias[col + 5], 0.f);
    o1.z = fmaxf(acc[6] * inv + bias[col + 6], 0.f);
    o1.w = fmaxf(acc[7] * inv + bias[col + 7], 0.f);
    float4* dst = (float4*)(out + (size_t)w * 256 + col);
    dst[0] = o0;
    dst[1] = o1;
}

__global__ __launch_bounds__(256) void gat_gather1_kernel(
    const int* __restrict__ rowptr, const int* __restrict__ adj,
    const __half* __restrict__ xl,
    const float* __restrict__ as_n, const float* __restrict__ ad_n,
    const float* __restrict__ bias, float* __restrict__ out, int N)
{
    int w = (blockIdx.x * blockDim.x + threadIdx.x) >> 5;
    int lane = threadIdx.x & 31;
    if (w >= N) return;

    const int col = lane * 2;
    const float ad = ad_n[w];

    float acc0 = 0.f, acc1 = 0.f, den = 0.f;

    int beg = rowptr[w], end = rowptr[w + 1];
    int j = beg;
    for (; j + 1 < end; j += 2) {
        int s0 = adj[j], s1 = adj[j + 1];
        float l0 = as_n[s0] + ad;
        float l1 = as_n[s1] + ad;
        l0 = (l0 > 0.f) ? l0 : 0.2f * l0;
        l1 = (l1 > 0.f) ? l1 : 0.2f * l1;
        float a0 = __expf(l0);
        float a1 = __expf(l1);
        float2 f0 = __half22float2(*(const __half2*)(xl + (size_t)s0 * 64 + col));
        float2 f1 = __half22float2(*(const __half2*)(xl + (size_t)s1 * 64 + col));
        den += a0 + a1;
        acc0 += a0 * f0.x + a1 * f1.x;
        acc1 += a0 * f0.y + a1 * f1.y;
    }
    if (j < end) {
        int s = adj[j];
        float l = as_n[s] + ad;
        l = (l > 0.f) ? l : 0.2f * l;
        float a = __expf(l);
        float2 f = __half22float2(*(const __half2*)(xl + (size_t)s * 64 + col));
        den += a;
        acc0 += a * f.x;
        acc1 += a * f.y;
    }

    float inv = 1.f / (den + 1e-16f);
    float2 o;
    o.x = fmaxf(acc0 * inv + bias[col + 0], 0.f);
    o.y = fmaxf(acc1 * inv + bias[col + 1], 0.f);
    *(float2*)(out + (size_t)w * 64 + col) = o;
}

// ---------------- host orchestration ----------------
extern "C" void kernel_launch(void* const* d_in, const int* in_sizes, int n_in,
                              void* d_out, int out_size)
{
    const float* x   = (const float*)d_in[0];
    const int*   ei  = (const int*)d_in[1];
    const float* W1  = (const float*)d_in[2];
    const float* as1 = (const float*)d_in[3];
    const float* ad1 = (const float*)d_in[4];
    const float* b1  = (const float*)d_in[5];
    const float* W2  = (const float*)d_in[6];
    const float* as2 = (const float*)d_in[7];
    const float* ad2 = (const float*)d_in[8];
    const float* b2  = (const float*)d_in[9];
    const float* W3  = (const float*)d_in[10];
    const float* as3 = (const float*)d_in[11];
    const float* ad3 = (const float*)d_in[12];
    const float* b3  = (const float*)d_in[13];
    const float* Wfc = (const float*)d_in[14];
    const float* bfc = (const float*)d_in[15];
    float* out = (float*)d_out;

    int N  = in_sizes[0] / kIN;
    int E  = in_sizes[1] / 2;
    int ET = E + N;

    float *bufA, *bufB, *bufC, *pas, *pad;
    int *rowptr, *deg, *adj, *bsum;
    cudaGetSymbolAddress((void**)&bufA, g_bufA);
    cudaGetSymbolAddress((void**)&bufB, g_bufB);
    cudaGetSymbolAddress((void**)&bufC, g_bufC);
    cudaGetSymbolAddress((void**)&pas,  g_as);
    cudaGetSymbolAddress((void**)&pad,  g_ad);
    cudaGetSymbolAddress((void**)&rowptr, g_rowptr);
    cudaGetSymbolAddress((void**)&deg,    g_deg);
    cudaGetSymbolAddress((void**)&adj,    g_adj);
    cudaGetSymbolAddress((void**)&bsum,   g_bsum);

    __half* bufAh = (__half*)bufA;

    // GEMM emitting half output (layers 1-3)
    auto gemm_h = [&](const float* A, const float* W, float* C, int M, int K, int Nc) {
        if (Nc % 128 == 0) {
            dim3 grid(Nc / 128, (M + 127) / 128);
            tgemm_kernel<128, true><<<grid, 256>>>(A, W, C, M, K, Nc, nullptr, 0);
        } else {
            dim3 grid(Nc / 64, (M + 127) / 128);
            tgemm_kernel<64, true><<<grid, 256>>>(A, W, C, M, K, Nc, nullptr, 0);
        }
    };

    int attnBlocks = (N + 7) / 8;
    int edgeBlocks = (ET + 255) / 256;
    int nodeWarpBlocks = (N + 7) / 8;
    int scanBlocks = (N + 1023) / 1024;

    // ---- CSR build ----
    cudaMemsetAsync(deg, 0, (size_t)N * sizeof(int));
    count_kernel<<<edgeBlocks, 256>>>(ei, E, N, deg);
    scan1_kernel<<<scanBlocks, 1024>>>(deg, rowptr, bsum, N);
    scan2_kernel<<<1, 32>>>(bsum, scanBlocks);
    scan3_kernel<<<scanBlocks, 1024>>>(rowptr, bsum, N);
    cudaMemsetAsync(deg, 0, (size_t)N * sizeof(int));
    fill_kernel<<<edgeBlocks, 256>>>(ei, E, N, rowptr, deg, adj);

    // ---- layer 1 ----
    gemm_h(x, W1, bufA, N, kIN, kHC);
    attn_coef_kernel<4, 64><<<attnBlocks, 256>>>(bufAh, as1, ad1, pas, pad, N);
    gat_gather4_kernel<<<nodeWarpBlocks, 256>>>(rowptr, adj, bufAh, pas, pad, b1, bufB, N);

    // ---- layer 2 ----
    gemm_h(bufB, W2, bufA, N, kHC, kHC);
    attn_coef_kernel<4, 64><<<attnBlocks, 256>>>(bufAh, as2, ad2, pas, pad, N);
    gat_gather4_kernel<<<nodeWarpBlocks, 256>>>(rowptr, adj, bufAh, pas, pad, b2, bufC, N);

    // ---- layer 3 ----
    gemm_h(bufC, W3, bufA, N, kHC, kC);
    attn_coef_kernel<1, 64><<<attnBlocks, 256>>>(bufAh, as3, ad3, pas, pad, N);
    gat_gather1_kernel<<<nodeWarpBlocks, 256>>>(rowptr, adj, bufAh, pas, pad, b3, bufB, N);

    // ---- final fc (fp32 out) ----
    {
        dim3 grid(kOUT / 128, (N + 127) / 128);
        tgemm_kernel<128, false><<<grid, 256>>>(bufB, Wfc, out, N, kC, kOUT, bfc, 1);
    }
}

// round 6
// speedup vs baseline: 5.6597x; 1.1078x over previous
#include <cuda_runtime.h>
#include <cuda_fp16.h>
#include <math.h>
#include <stdint.h>

// ---------------- problem constants ----------------
static constexpr int kIN  = 128;
static constexpr int kH   = 4;
static constexpr int kC   = 64;
static constexpr int kHC  = 256;
static constexpr int kOUT = 512;
static constexpr int MAXN  = 50000;
static constexpr int MAXET = 850000;

// ---------------- scratch ----------------
__device__ float g_bufA[(size_t)MAXN * kHC];
__device__ float g_bufB[(size_t)MAXN * kHC];
__device__ float g_bufC[(size_t)MAXN * kHC];
__device__ float g_as[(size_t)MAXN * kH];
__device__ float g_ad[(size_t)MAXN * kH];
__device__ int   g_rowptr[MAXN + 1];
__device__ int   g_deg[MAXN];
__device__ int   g_adj[MAXET];
__device__ int   g_bsum[256];

// ---------------- helpers ----------------
__device__ __forceinline__ uint32_t cvt_tf32(float f) {
    uint32_t u;
    asm("cvt.rna.tf32.f32 %0, %1;" : "=r"(u) : "f"(f));
    return u;
}

__device__ __forceinline__ void mma_tf32_16x8x8(float* c, const uint32_t* a, const uint32_t* b) {
    asm volatile(
        "mma.sync.aligned.m16n8k8.row.col.f32.tf32.tf32.f32 "
        "{%0,%1,%2,%3}, {%4,%5,%6,%7}, {%8,%9}, {%0,%1,%2,%3};"
        : "+f"(c[0]), "+f"(c[1]), "+f"(c[2]), "+f"(c[3])
        : "r"(a[0]), "r"(a[1]), "r"(a[2]), "r"(a[3]), "r"(b[0]), "r"(b[1]));
}

// ---------------- tf32 mma.sync GEMM with fused attn epilogue ----------------
// C[M,Nc] = A[M,K] @ W[K,Nc]; 128 x BN tile, BK=32, 8 warps 2(m)x4(n).
// HIN:  A stored as __half.   HOUT: C stored as __half.
// AH>0: also accumulate as_n/ad_n[row*AH + head] += sum_c C[row,c]*a{s,d}[c]
template <int BN, int AH, bool HIN, bool HOUT>
__global__ __launch_bounds__(256)
void tgemm_kernel(const void* __restrict__ Ain, const float* __restrict__ W,
                  void* __restrict__ Cout, int M, int K, int Nc,
                  const float* __restrict__ bias, int do_relu,
                  const float* __restrict__ avs, const float* __restrict__ avd,
                  float* __restrict__ as_n, float* __restrict__ ad_n)
{
    static constexpr int SA = 36;
    static constexpr int SB = BN + 8;
    static constexpr int NT = BN / 32;
    static constexpr int NB = 32 * (BN / 4) / 256;

    __shared__ uint32_t sA[128 * SA];
    __shared__ uint32_t sB[32 * SB];

    const int tid = threadIdx.x;
    const int wid = tid >> 5;
    const int lid = tid & 31;
    const int g   = lid >> 2;
    const int tig = lid & 3;
    const int warp_m = wid & 1;
    const int warp_n = wid >> 1;

    const int rowBase = blockIdx.y * 128;
    const int colBase = blockIdx.x * BN;

    float acc[4][NT][4];
#pragma unroll
    for (int mt = 0; mt < 4; mt++)
#pragma unroll
        for (int nt = 0; nt < NT; nt++)
#pragma unroll
            for (int i = 0; i < 4; i++) acc[mt][nt][i] = 0.f;

    float4 aRegF[4];
    uint4  aRegH[2];
    float4 wReg[NB];

    auto loadA = [&](int k0) {
        if (HIN) {
            const __half* A = (const __half*)Ain;
#pragma unroll
            for (int i = 0; i < 2; i++) {
                int idx = tid + 256 * i;          // 0..511 (8-half chunks)
                int m = idx >> 2, c8 = idx & 3;
                int gr = rowBase + m;
                aRegH[i] = (gr < M) ? *(const uint4*)(A + (size_t)gr * K + k0 + c8 * 8)
                                    : make_uint4(0u, 0u, 0u, 0u);
            }
        } else {
            const float* A = (const float*)Ain;
#pragma unroll
            for (int i = 0; i < 4; i++) {
                int idx = tid + 256 * i;
                int m = idx >> 3, c4 = idx & 7;
                int gr = rowBase + m;
                aRegF[i] = (gr < M) ? *(const float4*)(A + (size_t)gr * K + k0 + c4 * 4)
                                    : make_float4(0.f, 0.f, 0.f, 0.f);
            }
        }
    };
    auto loadW = [&](int k0) {
#pragma unroll
        for (int i = 0; i < NB; i++) {
            int idx = tid + 256 * i;
            int k = idx / (BN / 4), c4 = idx % (BN / 4);
            wReg[i] = *(const float4*)(W + (size_t)(k0 + k) * Nc + colBase + c4 * 4);
        }
    };
    auto stsTiles = [&]() {
        if (HIN) {
#pragma unroll
            for (int i = 0; i < 2; i++) {
                int idx = tid + 256 * i;
                int m = idx >> 2, c8 = idx & 3;
                const __half* hp = (const __half*)&aRegH[i];
                uint32_t t[8];
#pragma unroll
                for (int j = 0; j < 8; j++) t[j] = cvt_tf32(__half2float(hp[j]));
                *(uint4*)(sA + m * SA + c8 * 8)     = make_uint4(t[0], t[1], t[2], t[3]);
                *(uint4*)(sA + m * SA + c8 * 8 + 4) = make_uint4(t[4], t[5], t[6], t[7]);
            }
        } else {
#pragma unroll
            for (int i = 0; i < 4; i++) {
                int idx = tid + 256 * i;
                int m = idx >> 3, c4 = idx & 7;
                float4 v = aRegF[i];
                *(uint4*)(sA + m * SA + c4 * 4) =
                    make_uint4(cvt_tf32(v.x), cvt_tf32(v.y), cvt_tf32(v.z), cvt_tf32(v.w));
            }
        }
#pragma unroll
        for (int i = 0; i < NB; i++) {
            int idx = tid + 256 * i;
            int k = idx / (BN / 4), c4 = idx % (BN / 4);
            float4 v = wReg[i];
            *(uint4*)(sB + k * SB + c4 * 4) =
                make_uint4(cvt_tf32(v.x), cvt_tf32(v.y), cvt_tf32(v.z), cvt_tf32(v.w));
        }
    };

    const int nchunk = K / 32;
    loadA(0);
    loadW(0);

    for (int ch = 0; ch < nchunk; ch++) {
        stsTiles();
        __syncthreads();
        if (ch + 1 < nchunk) { loadA((ch + 1) * 32); loadW((ch + 1) * 32); }

#pragma unroll
        for (int kk = 0; kk < 4; kk++) {
            const int kb = kk * 8;
            uint32_t afr[4][4];
#pragma unroll
            for (int mt = 0; mt < 4; mt++) {
                int m = warp_m * 64 + mt * 16 + g;
                afr[mt][0] = sA[(m)     * SA + kb + tig];
                afr[mt][1] = sA[(m + 8) * SA + kb + tig];
                afr[mt][2] = sA[(m)     * SA + kb + tig + 4];
                afr[mt][3] = sA[(m + 8) * SA + kb + tig + 4];
            }
            uint32_t bfr[NT][2];
#pragma unroll
            for (int nt = 0; nt < NT; nt++) {
                int n = warp_n * (BN / 4) + nt * 8 + g;
                bfr[nt][0] = sB[(kb + tig)     * SB + n];
                bfr[nt][1] = sB[(kb + tig + 4) * SB + n];
            }
#pragma unroll
            for (int mt = 0; mt < 4; mt++)
#pragma unroll
                for (int nt = 0; nt < NT; nt++)
                    mma_tf32_16x8x8(acc[mt][nt], afr[mt], bfr[nt]);
        }
        __syncthreads();
    }

    // ---- fused attn partials: as/ad[row, head] += sum_c acc*a[c] ----
    if (AH > 0) {
        const int h = (AH == 1) ? 0 : ((colBase + warp_n * (BN / 4)) >> 6);
#pragma unroll
        for (int mt = 0; mt < 4; mt++) {
            float s0 = 0.f, s1 = 0.f, d0 = 0.f, d1 = 0.f;
#pragma unroll
            for (int nt = 0; nt < NT; nt++) {
                int col = colBase + warp_n * (BN / 4) + nt * 8 + tig * 2;
                float a0 = avs[col], a1 = avs[col + 1];
                float b0 = avd[col], b1 = avd[col + 1];
                s0 += acc[mt][nt][0] * a0 + acc[mt][nt][1] * a1;
                s1 += acc[mt][nt][2] * a0 + acc[mt][nt][3] * a1;
                d0 += acc[mt][nt][0] * b0 + acc[mt][nt][1] * b1;
                d1 += acc[mt][nt][2] * b0 + acc[mt][nt][3] * b1;
            }
#pragma unroll
            for (int off = 1; off <= 2; off <<= 1) {
                s0 += __shfl_xor_sync(0xFFFFFFFFu, s0, off);
                s1 += __shfl_xor_sync(0xFFFFFFFFu, s1, off);
                d0 += __shfl_xor_sync(0xFFFFFFFFu, d0, off);
                d1 += __shfl_xor_sync(0xFFFFFFFFu, d1, off);
            }
            if (tig == 0) {
                int row0 = rowBase + warp_m * 64 + mt * 16 + g;
                int row1 = row0 + 8;
                if (row0 < M) {
                    atomicAdd(&as_n[(size_t)row0 * AH + h], s0);
                    atomicAdd(&ad_n[(size_t)row0 * AH + h], d0);
                }
                if (row1 < M) {
                    atomicAdd(&as_n[(size_t)row1 * AH + h], s1);
                    atomicAdd(&ad_n[(size_t)row1 * AH + h], d1);
                }
            }
        }
    }

    // ---- store C ----
#pragma unroll
    for (int mt = 0; mt < 4; mt++) {
        int row0 = rowBase + warp_m * 64 + mt * 16 + g;
        int row1 = row0 + 8;
#pragma unroll
        for (int nt = 0; nt < NT; nt++) {
            int col = colBase + warp_n * (BN / 4) + nt * 8 + tig * 2;
            float bx = 0.f, by = 0.f;
            if (bias) { bx = bias[col]; by = bias[col + 1]; }
            float2 v0 = make_float2(acc[mt][nt][0] + bx, acc[mt][nt][1] + by);
            float2 v1 = make_float2(acc[mt][nt][2] + bx, acc[mt][nt][3] + by);
            if (do_relu) {
                v0.x = fmaxf(v0.x, 0.f); v0.y = fmaxf(v0.y, 0.f);
                v1.x = fmaxf(v1.x, 0.f); v1.y = fmaxf(v1.y, 0.f);
            }
            if (HOUT) {
                __half2* Ch = (__half2*)Cout;
                if (row0 < M) Ch[((size_t)row0 * Nc + col) >> 1] = __float22half2_rn(v0);
                if (row1 < M) Ch[((size_t)row1 * Nc + col) >> 1] = __float22half2_rn(v1);
            } else {
                float* Cf = (float*)Cout;
                if (row0 < M) *(float2*)(Cf + (size_t)row0 * Nc + col) = v0;
                if (row1 < M) *(float2*)(Cf + (size_t)row1 * Nc + col) = v1;
            }
        }
    }
}

// ---------------- CSR build ----------------
__global__ void count_kernel(const int* __restrict__ ei, int E, int N, int* __restrict__ deg)
{
    int e = blockIdx.x * blockDim.x + threadIdx.x;
    int ET = E + N;
    if (e >= ET) return;
    int d = (e < E) ? ei[E + e] : (e - E);
    atomicAdd(&deg[d], 1);
}

__global__ void scan1_kernel(const int* __restrict__ deg, int* __restrict__ rowptr,
                             int* __restrict__ bsum, int N)
{
    __shared__ int sh[1024];
    int i = blockIdx.x * 1024 + threadIdx.x;
    int v = (i < N) ? deg[i] : 0;
    sh[threadIdx.x] = v;
    __syncthreads();
#pragma unroll
    for (int off = 1; off < 1024; off <<= 1) {
        int t = (threadIdx.x >= off) ? sh[threadIdx.x - off] : 0;
        __syncthreads();
        sh[threadIdx.x] += t;
        __syncthreads();
    }
    if (i < N) rowptr[i + 1] = sh[threadIdx.x];
    if (threadIdx.x == 1023) bsum[blockIdx.x] = sh[1023];
}

__global__ void scan2_kernel(int* __restrict__ bsum, int nb)
{
    if (threadIdx.x == 0) {
        int acc = 0;
        for (int i = 0; i < nb; i++) { int t = bsum[i]; bsum[i] = acc; acc += t; }
    }
}

__global__ void scan3_kernel(int* __restrict__ rowptr, const int* __restrict__ bsum, int N)
{
    int i = blockIdx.x * 1024 + threadIdx.x;
    if (i < N) rowptr[i + 1] += bsum[blockIdx.x];
    if (i == 0) rowptr[0] = 0;
}

__global__ void fill_kernel(const int* __restrict__ ei, int E, int N,
                            const int* __restrict__ rowptr, int* __restrict__ cur,
                            int* __restrict__ adj)
{
    int e = blockIdx.x * blockDim.x + threadIdx.x;
    int ET = E + N;
    if (e >= ET) return;
    int s, d;
    if (e < E) { s = ei[e]; d = ei[E + e]; } else { s = d = e - E; }
    int pos = rowptr[d] + atomicAdd(&cur[d], 1);
    adj[pos] = s;
}

// ---------------- fused gather (half in, half out) ----------------
__device__ __forceinline__ void acc8_half(float* acc, float a, uint4 r)
{
    const __half2* hp = (const __half2*)&r;
#pragma unroll
    for (int i = 0; i < 4; i++) {
        float2 f = __half22float2(hp[i]);
        acc[2 * i]     += a * f.x;
        acc[2 * i + 1] += a * f.y;
    }
}

__global__ __launch_bounds__(256) void gat_gather4_kernel(
    const int* __restrict__ rowptr, const int* __restrict__ adj,
    const __half* __restrict__ xl,
    const float* __restrict__ as_n, const float* __restrict__ ad_n,
    const float* __restrict__ bias, __half* __restrict__ out, int N)
{
    int w = (blockIdx.x * blockDim.x + threadIdx.x) >> 5;
    int lane = threadIdx.x & 31;
    if (w >= N) return;

    const int h   = lane >> 3;
    const int col = lane * 8;
    const float ad = ad_n[(size_t)w * 4 + h];

    float acc[8];
#pragma unroll
    for (int i = 0; i < 8; i++) acc[i] = 0.f;
    float den = 0.f;

    int beg = rowptr[w], end = rowptr[w + 1];
    int j = beg;
    for (; j + 1 < end; j += 2) {
        int s0 = adj[j], s1 = adj[j + 1];
        float l0 = as_n[(size_t)s0 * 4 + h] + ad;
        float l1 = as_n[(size_t)s1 * 4 + h] + ad;
        l0 = (l0 > 0.f) ? l0 : 0.2f * l0;
        l1 = (l1 > 0.f) ? l1 : 0.2f * l1;
        float a0 = __expf(l0);
        float a1 = __expf(l1);
        uint4 r0 = *(const uint4*)(xl + (size_t)s0 * 256 + col);
        uint4 r1 = *(const uint4*)(xl + (size_t)s1 * 256 + col);
        den += a0 + a1;
        acc8_half(acc, a0, r0);
        acc8_half(acc, a1, r1);
    }
    if (j < end) {
        int s = adj[j];
        float l = as_n[(size_t)s * 4 + h] + ad;
        l = (l > 0.f) ? l : 0.2f * l;
        float a = __expf(l);
        uint4 r = *(const uint4*)(xl + (size_t)s * 256 + col);
        den += a;
        acc8_half(acc, a, r);
    }

    float inv = 1.f / (den + 1e-16f);
    __half2 o[4];
#pragma unroll
    for (int i = 0; i < 4; i++) {
        float2 f;
        f.x = fmaxf(acc[2 * i]     * inv + bias[col + 2 * i],     0.f);
        f.y = fmaxf(acc[2 * i + 1] * inv + bias[col + 2 * i + 1], 0.f);
        o[i] = __float22half2_rn(f);
    }
    *(uint4*)(out + (size_t)w * 256 + col) = *(const uint4*)o;
}

__global__ __launch_bounds__(256) void gat_gather1_kernel(
    const int* __restrict__ rowptr, const int* __restrict__ adj,
    const __half* __restrict__ xl,
    const float* __restrict__ as_n, const float* __restrict__ ad_n,
    const float* __restrict__ bias, __half* __restrict__ out, int N)
{
    int w = (blockIdx.x * blockDim.x + threadIdx.x) >> 5;
    int lane = threadIdx.x & 31;
    if (w >= N) return;

    const int col = lane * 2;
    const float ad = ad_n[w];

    float acc0 = 0.f, acc1 = 0.f, den = 0.f;

    int beg = rowptr[w], end = rowptr[w + 1];
    int j = beg;
    for (; j + 1 < end; j += 2) {
        int s0 = adj[j], s1 = adj[j + 1];
        float l0 = as_n[s0] + ad;
        float l1 = as_n[s1] + ad;
        l0 = (l0 > 0.f) ? l0 : 0.2f * l0;
        l1 = (l1 > 0.f) ? l1 : 0.2f * l1;
        float a0 = __expf(l0);
        float a1 = __expf(l1);
        float2 f0 = __half22float2(*(const __half2*)(xl + (size_t)s0 * 64 + col));
        float2 f1 = __half22float2(*(const __half2*)(xl + (size_t)s1 * 64 + col));
        den += a0 + a1;
        acc0 += a0 * f0.x + a1 * f1.x;
        acc1 += a0 * f0.y + a1 * f1.y;
    }
    if (j < end) {
        int s = adj[j];
        float l = as_n[s] + ad;
        l = (l > 0.f) ? l : 0.2f * l;
        float a = __expf(l);
        float2 f = __half22float2(*(const __half2*)(xl + (size_t)s * 64 + col));
        den += a;
        acc0 += a * f.x;
        acc1 += a * f.y;
    }

    float inv = 1.f / (den + 1e-16f);
    float2 f;
    f.x = fmaxf(acc0 * inv + bias[col + 0], 0.f);
    f.y = fmaxf(acc1 * inv + bias[col + 1], 0.f);
    *(__half2*)(out + (size_t)w * 64 + col) = __float22half2_rn(f);
}

// ---------------- host orchestration ----------------
extern "C" void kernel_launch(void* const* d_in, const int* in_sizes, int n_in,
                              void* d_out, int out_size)
{
    const float* x   = (const float*)d_in[0];
    const int*   ei  = (const int*)d_in[1];
    const float* W1  = (const float*)d_in[2];
    const float* as1 = (const float*)d_in[3];
    const float* ad1 = (const float*)d_in[4];
    const float* b1  = (const float*)d_in[5];
    const float* W2  = (const float*)d_in[6];
    const float* as2 = (const float*)d_in[7];
    const float* ad2 = (const float*)d_in[8];
    const float* b2  = (const float*)d_in[9];
    const float* W3  = (const float*)d_in[10];
    const float* as3 = (const float*)d_in[11];
    const float* ad3 = (const float*)d_in[12];
    const float* b3  = (const float*)d_in[13];
    const float* Wfc = (const float*)d_in[14];
    const float* bfc = (const float*)d_in[15];
    float* out = (float*)d_out;

    int N  = in_sizes[0] / kIN;
    int E  = in_sizes[1] / 2;
    int ET = E + N;

    float *bufA, *bufB, *bufC, *pas, *pad;
    int *rowptr, *deg, *adj, *bsum;
    cudaGetSymbolAddress((void**)&bufA, g_bufA);
    cudaGetSymbolAddress((void**)&bufB, g_bufB);
    cudaGetSymbolAddress((void**)&bufC, g_bufC);
    cudaGetSymbolAddress((void**)&pas,  g_as);
    cudaGetSymbolAddress((void**)&pad,  g_ad);
    cudaGetSymbolAddress((void**)&rowptr, g_rowptr);
    cudaGetSymbolAddress((void**)&deg,    g_deg);
    cudaGetSymbolAddress((void**)&adj,    g_adj);
    cudaGetSymbolAddress((void**)&bsum,   g_bsum);

    __half* bufAh = (__half*)bufA;
    __half* bufBh = (__half*)bufB;
    __half* bufCh = (__half*)bufC;

    int edgeBlocks = (ET + 255) / 256;
    int nodeWarpBlocks = (N + 7) / 8;
    int scanBlocks = (N + 1023) / 1024;

    dim3 grid256((kHC + 127) / 128, (N + 127) / 128);
    dim3 grid64(1, (N + 127) / 128);
    dim3 gridFC(kOUT / 128, (N + 127) / 128);

    // ---- CSR build ----
    cudaMemsetAsync(deg, 0, (size_t)N * sizeof(int));
    count_kernel<<<edgeBlocks, 256>>>(ei, E, N, deg);
    scan1_kernel<<<scanBlocks, 1024>>>(deg, rowptr, bsum, N);
    scan2_kernel<<<1, 32>>>(bsum, scanBlocks);
    scan3_kernel<<<scanBlocks, 1024>>>(rowptr, bsum, N);
    cudaMemsetAsync(deg, 0, (size_t)N * sizeof(int));
    fill_kernel<<<edgeBlocks, 256>>>(ei, E, N, rowptr, deg, adj);

    // ---- layer 1: x fp32 -> xl half + fused attn ----
    cudaMemsetAsync(pas, 0, (size_t)N * kH * sizeof(float));
    cudaMemsetAsync(pad, 0, (size_t)N * kH * sizeof(float));
    tgemm_kernel<128, 4, false, true><<<grid256, 256>>>(
        x, W1, bufA, N, kIN, kHC, nullptr, 0, as1, ad1, pas, pad);
    gat_gather4_kernel<<<nodeWarpBlocks, 256>>>(rowptr, adj, bufAh, pas, pad, b1, bufBh, N);

    // ---- layer 2 ----
    cudaMemsetAsync(pas, 0, (size_t)N * kH * sizeof(float));
    cudaMemsetAsync(pad, 0, (size_t)N * kH * sizeof(float));
    tgemm_kernel<128, 4, true, true><<<grid256, 256>>>(
        bufBh, W2, bufA, N, kHC, kHC, nullptr, 0, as2, ad2, pas, pad);
    gat_gather4_kernel<<<nodeWarpBlocks, 256>>>(rowptr, adj, bufAh, pas, pad, b2, bufCh, N);

    // ---- layer 3 (1 head, Nc=64) ----
    cudaMemsetAsync(pas, 0, (size_t)N * sizeof(float));
    cudaMemsetAsync(pad, 0, (size_t)N * sizeof(float));
    tgemm_kernel<64, 1, true, true><<<grid64, 256>>>(
        bufCh, W3, bufA, N, kHC, kC, nullptr, 0, as3, ad3, pas, pad);
    gat_gather1_kernel<<<nodeWarpBlocks, 256>>>(rowptr, adj, bufAh, pas, pad, b3, bufBh, N);

    // ---- final fc: half A -> fp32 out (+bias, relu) ----
    tgemm_kernel<128, 0, true, false><<<gridFC, 256>>>(
        bufBh, Wfc, out, N, kC, kOUT, bfc, 1, nullptr, nullptr, nullptr, nullptr);
}